// round 2
// baseline (speedup 1.0000x reference)
#include <cuda_runtime.h>
#include <stdint.h>

// Problem constants (fixed shapes from the reference setup)
#define N_NODES 100000
#define N_PAIRS 1600000
#define F 64
#define H 4
#define D 16

// Scratch (static __device__ — no runtime allocation allowed)
__device__ float g_q[(size_t)N_NODES * F];
__device__ float g_k[(size_t)N_NODES * F];
__device__ float g_v[(size_t)N_NODES * F];
__device__ int   g_rowstart[N_NODES + 1];
__device__ int   g_idx_i[N_PAIRS];
__device__ int   g_idx_j[N_PAIRS];
__device__ int   g_is64;

// ---------------------------------------------------------------------------
// Kernel 0a: detect whether the index buffers are int64 or int32.
// View idx_j as int32 pairs; for genuine int64 data (values < 100000) every
// high word is 0. For int32 data the sampled words are random node indices.
// ---------------------------------------------------------------------------
__global__ void detect_kernel(const int* __restrict__ idx_j32)
{
    int nz = 0;
    #pragma unroll
    for (int s = 0; s < 64; ++s)
        nz |= idx_j32[2 * s + 1];
    g_is64 = (nz == 0) ? 1 : 0;
}

// Kernel 0b: normalize both index arrays to int.
__global__ void convert_kernel(const void* __restrict__ idx_i,
                               const void* __restrict__ idx_j)
{
    int p = blockIdx.x * blockDim.x + threadIdx.x;
    if (p >= N_PAIRS) return;
    if (g_is64) {
        g_idx_i[p] = (int)((const long long*)idx_i)[p];
        g_idx_j[p] = (int)((const long long*)idx_j)[p];
    } else {
        g_idx_i[p] = ((const int*)idx_i)[p];
        g_idx_j[p] = ((const int*)idx_j)[p];
    }
}

// ---------------------------------------------------------------------------
// Kernel 1: per-node, per-head projections  q/k/v[n,h,:] = x[n,h,:] @ W*[h]
// Block = 256 threads = 16 nodes x 16 thread-groups; each thread computes a
// float4 slice of the 64 output elements for all three projections.
// ---------------------------------------------------------------------------
#define NODES_PER_BLOCK 16

__global__ void project_kernel(const float* __restrict__ x,
                               const float* __restrict__ Wq,
                               const float* __restrict__ Wk,
                               const float* __restrict__ Wv)
{
    __shared__ float sW[3][H * D * D];           // 12 KB
    __shared__ float sx[NODES_PER_BLOCK][F];     // 4 KB

    const int tid = threadIdx.x;

    for (int idx = tid; idx < H * D * D; idx += 256) {
        sW[0][idx] = Wq[idx];
        sW[1][idx] = Wk[idx];
        sW[2][idx] = Wv[idx];
    }
    const int node0 = blockIdx.x * NODES_PER_BLOCK;
    for (int idx = tid; idx < NODES_PER_BLOCK * F; idx += 256) {
        int node = node0 + (idx >> 6);
        ((float*)sx)[idx] = (node < N_NODES) ? x[(size_t)node * F + (idx & 63)] : 0.f;
    }
    __syncthreads();

    const int nl = tid >> 4;          // node within block
    const int e4 = tid & 15;          // which float4 of the 64 outputs
    const int h  = e4 >> 2;           // head
    const int c4 = (e4 & 3) * 4;      // column offset within head

    const int node = node0 + nl;
    if (node >= N_NODES) return;

    const float* xr = &sx[nl][h * D];

    float4 aq = make_float4(0.f, 0.f, 0.f, 0.f);
    float4 ak = aq, av = aq;

    #pragma unroll
    for (int d = 0; d < D; ++d) {
        float xd = xr[d];
        float4 wq = *(const float4*)&sW[0][h * 256 + d * 16 + c4];
        float4 wk = *(const float4*)&sW[1][h * 256 + d * 16 + c4];
        float4 wv = *(const float4*)&sW[2][h * 256 + d * 16 + c4];
        aq.x = fmaf(xd, wq.x, aq.x); aq.y = fmaf(xd, wq.y, aq.y);
        aq.z = fmaf(xd, wq.z, aq.z); aq.w = fmaf(xd, wq.w, aq.w);
        ak.x = fmaf(xd, wk.x, ak.x); ak.y = fmaf(xd, wk.y, ak.y);
        ak.z = fmaf(xd, wk.z, ak.z); ak.w = fmaf(xd, wk.w, ak.w);
        av.x = fmaf(xd, wv.x, av.x); av.y = fmaf(xd, wv.y, av.y);
        av.z = fmaf(xd, wv.z, av.z); av.w = fmaf(xd, wv.w, av.w);
    }

    const size_t base = (size_t)node * F + e4 * 4;
    *(float4*)&g_q[base] = aq;
    *(float4*)&g_k[base] = ak;
    *(float4*)&g_v[base] = av;
}

// ---------------------------------------------------------------------------
// Kernel 2: build CSR row offsets from the SORTED g_idx_i.
// ---------------------------------------------------------------------------
__global__ void build_rowptr_kernel()
{
    int p = blockIdx.x * blockDim.x + threadIdx.x;
    if (p >= N_PAIRS) return;
    int i    = g_idx_i[p];
    int prev = (p == 0) ? -1 : g_idx_i[p - 1];
    for (int node = prev + 1; node <= i; ++node)
        g_rowstart[node] = p;
    if (p == N_PAIRS - 1) {
        for (int node = i + 1; node <= N_NODES; ++node)
            g_rowstart[node] = N_PAIRS;
    }
}

// ---------------------------------------------------------------------------
// Kernel 3: warp-per-node fused attention + segment sum (no atomics).
// Lane l owns output elements l and l+32. Head dot-products reduce via
// 16-lane shuffle butterflies (reg0: heads 0/1, reg1: heads 2/3).
// ---------------------------------------------------------------------------
__global__ void __launch_bounds__(256) attn_kernel(
    const float* __restrict__ w_ij,
    const float* __restrict__ phi,
    const float* __restrict__ pmask,
    float* __restrict__ out)
{
    const int warp = (blockIdx.x * blockDim.x + threadIdx.x) >> 5;
    const int lane = threadIdx.x & 31;
    if (warp >= N_NODES) return;
    const int i = warp;

    const int p0 = g_rowstart[i];
    const int p1 = g_rowstart[i + 1];

    const float q0 = g_q[(size_t)i * F + lane];
    const float q1 = g_q[(size_t)i * F + 32 + lane];

    float acc0 = 0.f, acc1 = 0.f;

    if (p0 < p1) {
        int   j  = g_idx_j[p0];
        float sc = phi[p0] * pmask[p0] * 0.25f;   // 1/sqrt(16) = 0.25

        for (int p = p0; p < p1; ++p) {
            int jn = 0; float scn = 0.f;
            if (p + 1 < p1) {
                jn  = g_idx_j[p + 1];
                scn = phi[p + 1] * pmask[p + 1] * 0.25f;
            }

            const float* wr = w_ij + (size_t)p * F;
            const float* kr = g_k  + (size_t)j * F;
            const float* vr = g_v  + (size_t)j * F;

            float w0 = wr[lane], w1 = wr[lane + 32];
            float k0 = kr[lane], k1 = kr[lane + 32];
            float v0 = vr[lane], v1 = vr[lane + 32];

            float t0 = q0 * w0 * k0;
            float t1 = q1 * w1 * k1;

            #pragma unroll
            for (int m = 8; m >= 1; m >>= 1) {
                t0 += __shfl_xor_sync(0xffffffffu, t0, m, 16);
                t1 += __shfl_xor_sync(0xffffffffu, t1, m, 16);
            }

            acc0 = fmaf(t0 * sc, v0, acc0);
            acc1 = fmaf(t1 * sc, v1, acc1);

            j = jn; sc = scn;
        }
    }

    out[(size_t)i * F + lane]      = acc0;
    out[(size_t)i * F + 32 + lane] = acc1;
}

// ---------------------------------------------------------------------------
extern "C" void kernel_launch(void* const* d_in, const int* in_sizes, int n_in,
                              void* d_out, int out_size)
{
    const float* x     = (const float*)d_in[0];
    const float* w_ij  = (const float*)d_in[1];
    const float* phi   = (const float*)d_in[2];
    const float* pmask = (const float*)d_in[3];
    const float* Wq    = (const float*)d_in[4];
    const float* Wk    = (const float*)d_in[5];
    const float* Wv    = (const float*)d_in[6];
    const void*  idx_i = d_in[7];
    const void*  idx_j = d_in[8];
    float* out = (float*)d_out;

    // 0) normalize index dtype (int32 vs int64) into int scratch
    detect_kernel<<<1, 1>>>((const int*)idx_j);
    convert_kernel<<<(N_PAIRS + 255) / 256, 256>>>(idx_i, idx_j);

    // 1) projections
    project_kernel<<<(N_NODES + NODES_PER_BLOCK - 1) / NODES_PER_BLOCK, 256>>>(x, Wq, Wk, Wv);

    // 2) CSR offsets from sorted idx_i
    build_rowptr_kernel<<<(N_PAIRS + 255) / 256, 256>>>();

    // 3) fused attention + segment sum, warp per node
    attn_kernel<<<(N_NODES + 7) / 8, 256>>>(w_ij, phi, pmask, out);
}

// round 4
// speedup vs baseline: 1.0754x; 1.0754x over previous
#include <cuda_runtime.h>
#include <stdint.h>

#define N_NODES 100000
#define N_PAIRS 1600000
#define F 64
#define H 4
#define D 16

// Scratch (static __device__ — no runtime allocation allowed)
__device__ float g_q[(size_t)N_NODES * F];
__device__ float g_k[(size_t)N_NODES * F];
__device__ float g_v[(size_t)N_NODES * F];
__device__ int   g_rowstart[N_NODES + 1];
__device__ int   g_idx_j[N_PAIRS];
__device__ float g_scale[N_PAIRS];
__device__ int   g_is64;

// ---------------------------------------------------------------------------
// Kernel 0a: detect int64 vs int32 index buffers.
// For true int64 (values < 100000) every high word is 0; for int32 the odd
// words are random node indices (P[all 64 zero] ~ 0).
// ---------------------------------------------------------------------------
__global__ void detect_kernel(const int* __restrict__ idx_j32)
{
    int nz = 0;
    #pragma unroll
    for (int s = 0; s < 64; ++s)
        nz |= idx_j32[2 * s + 1];
    g_is64 = (nz == 0) ? 1 : 0;
}

// Kernel 0b: normalize idx_j to int and fuse the per-pair scalar product.
__global__ void convert_kernel(const void* __restrict__ idx_j,
                               const float* __restrict__ phi,
                               const float* __restrict__ pmask)
{
    int p = blockIdx.x * blockDim.x + threadIdx.x;
    if (p >= N_PAIRS) return;
    g_idx_j[p] = g_is64 ? (int)((const long long*)idx_j)[p]
                        : ((const int*)idx_j)[p];
    g_scale[p] = phi[p] * pmask[p] * 0.25f;   // 1/sqrt(16) = 0.25
}

// ---------------------------------------------------------------------------
// Kernel 1: per-node per-head projections, staged weights + x in SMEM.
// ---------------------------------------------------------------------------
#define NODES_PER_BLOCK 16

__global__ void project_kernel(const float* __restrict__ x,
                               const float* __restrict__ Wq,
                               const float* __restrict__ Wk,
                               const float* __restrict__ Wv)
{
    __shared__ float sW[3][H * D * D];
    __shared__ float sx[NODES_PER_BLOCK][F];

    const int tid = threadIdx.x;

    for (int idx = tid; idx < H * D * D; idx += 256) {
        sW[0][idx] = Wq[idx];
        sW[1][idx] = Wk[idx];
        sW[2][idx] = Wv[idx];
    }
    const int node0 = blockIdx.x * NODES_PER_BLOCK;
    for (int idx = tid; idx < NODES_PER_BLOCK * F; idx += 256) {
        int node = node0 + (idx >> 6);
        ((float*)sx)[idx] = (node < N_NODES) ? x[(size_t)node * F + (idx & 63)] : 0.f;
    }
    __syncthreads();

    const int nl = tid >> 4;
    const int e4 = tid & 15;
    const int h  = e4 >> 2;
    const int c4 = (e4 & 3) * 4;

    const int node = node0 + nl;
    if (node >= N_NODES) return;

    const float* xr = &sx[nl][h * D];

    float4 aq = make_float4(0.f, 0.f, 0.f, 0.f);
    float4 ak = aq, av = aq;

    #pragma unroll
    for (int d = 0; d < D; ++d) {
        float xd = xr[d];
        float4 wq = *(const float4*)&sW[0][h * 256 + d * 16 + c4];
        float4 wk = *(const float4*)&sW[1][h * 256 + d * 16 + c4];
        float4 wv = *(const float4*)&sW[2][h * 256 + d * 16 + c4];
        aq.x = fmaf(xd, wq.x, aq.x); aq.y = fmaf(xd, wq.y, aq.y);
        aq.z = fmaf(xd, wq.z, aq.z); aq.w = fmaf(xd, wq.w, aq.w);
        ak.x = fmaf(xd, wk.x, ak.x); ak.y = fmaf(xd, wk.y, ak.y);
        ak.z = fmaf(xd, wk.z, ak.z); ak.w = fmaf(xd, wk.w, ak.w);
        av.x = fmaf(xd, wv.x, av.x); av.y = fmaf(xd, wv.y, av.y);
        av.z = fmaf(xd, wv.z, av.z); av.w = fmaf(xd, wv.w, av.w);
    }

    const size_t base = (size_t)node * F + e4 * 4;
    *(float4*)&g_q[base] = aq;
    *(float4*)&g_k[base] = ak;
    *(float4*)&g_v[base] = av;
}

// ---------------------------------------------------------------------------
// Kernel 2: CSR row offsets straight from the SORTED raw idx_i.
// ---------------------------------------------------------------------------
__global__ void build_rowptr_kernel(const void* __restrict__ idx_i)
{
    int p = blockIdx.x * blockDim.x + threadIdx.x;
    if (p >= N_PAIRS) return;
    int i, prev;
    if (g_is64) {
        const long long* ii = (const long long*)idx_i;
        i    = (int)ii[p];
        prev = (p == 0) ? -1 : (int)ii[p - 1];
    } else {
        const int* ii = (const int*)idx_i;
        i    = ii[p];
        prev = (p == 0) ? -1 : ii[p - 1];
    }
    for (int node = prev + 1; node <= i; ++node)
        g_rowstart[node] = p;
    if (p == N_PAIRS - 1) {
        for (int node = i + 1; node <= N_NODES; ++node)
            g_rowstart[node] = N_PAIRS;
    }
}

// ---------------------------------------------------------------------------
// Kernel 3: warp-per-node fused attention + segment sum.
// Half-warp per pair: 16 lanes x float4 = full 64-float row; two pairs per
// iteration. UNIFORM trip count across the warp (invalid slots contribute 0)
// so every lane executes every shuffle -> no divergence deadlock. Head
// reduction = 2 shuffles within 4-lane groups. No atomics.
// ---------------------------------------------------------------------------
__global__ void __launch_bounds__(256) attn_kernel(
    const float* __restrict__ w_ij,
    float* __restrict__ out)
{
    const int warp = (blockIdx.x * blockDim.x + threadIdx.x) >> 5;
    const int lane = threadIdx.x & 31;
    if (warp >= N_NODES) return;
    const int i    = warp;
    const int half = lane >> 4;               // which pair of the pair-pair
    const int sl   = lane & 15;               // float4 slot within the row
    const unsigned gmask = 0xFu << (lane & 28);  // this lane's 4-lane head group

    const int p0 = g_rowstart[i];
    const int p1 = g_rowstart[i + 1];
    const int n  = p1 - p0;
    const int iters = (n + 1) >> 1;           // uniform across the whole warp

    // q row, loaded once (same for both halves)
    const float4 q4 = *(const float4*)&g_q[(size_t)i * F + sl * 4];

    float4 acc = make_float4(0.f, 0.f, 0.f, 0.f);

    // pipeline the per-pair scalars one iteration ahead
    int   p_cur  = p0 + half;
    bool  v_cur  = (p_cur < p1);
    int   pc_cur = v_cur ? p_cur : p0;
    int   j_cur  = (iters > 0) ? g_idx_j[pc_cur] : 0;
    float s_cur  = (iters > 0 && v_cur) ? g_scale[pc_cur] : 0.f;

    for (int it = 0; it < iters; ++it) {
        // prefetch next iteration's scalars
        int   j_nxt = 0;  float s_nxt = 0.f;  int pc_nxt = p0;
        if (it + 1 < iters) {
            int  p_n = p0 + 2 * (it + 1) + half;
            bool v_n = (p_n < p1);
            pc_nxt   = v_n ? p_n : p0;
            j_nxt    = g_idx_j[pc_nxt];
            s_nxt    = v_n ? g_scale[pc_nxt] : 0.f;
        }

        const float4 w4 = *(const float4*)&w_ij[(size_t)pc_cur * F + sl * 4];
        const float4 k4 = *(const float4*)&g_k [(size_t)j_cur  * F + sl * 4];
        const float4 v4 = *(const float4*)&g_v [(size_t)j_cur  * F + sl * 4];

        // partial head dot product: this lane's 4 elements
        float t = q4.x * w4.x * k4.x;
        t = fmaf(q4.y * w4.y, k4.y, t);
        t = fmaf(q4.z * w4.z, k4.z, t);
        t = fmaf(q4.w * w4.w, k4.w, t);

        // reduce across the 4 lanes of this head group
        t += __shfl_xor_sync(gmask, t, 1, 4);
        t += __shfl_xor_sync(gmask, t, 2, 4);

        const float a = t * s_cur;             // s_cur==0 for padded slots
        acc.x = fmaf(a, v4.x, acc.x);
        acc.y = fmaf(a, v4.y, acc.y);
        acc.z = fmaf(a, v4.z, acc.z);
        acc.w = fmaf(a, v4.w, acc.w);

        pc_cur = pc_nxt; j_cur = j_nxt; s_cur = s_nxt;
    }

    // merge the two half-warp accumulators (warp fully converged here)
    acc.x += __shfl_xor_sync(0xffffffffu, acc.x, 16);
    acc.y += __shfl_xor_sync(0xffffffffu, acc.y, 16);
    acc.z += __shfl_xor_sync(0xffffffffu, acc.z, 16);
    acc.w += __shfl_xor_sync(0xffffffffu, acc.w, 16);

    if (half == 0)
        *(float4*)&out[(size_t)i * F + sl * 4] = acc;
}

// ---------------------------------------------------------------------------
extern "C" void kernel_launch(void* const* d_in, const int* in_sizes, int n_in,
                              void* d_out, int out_size)
{
    const float* x     = (const float*)d_in[0];
    const float* w_ij  = (const float*)d_in[1];
    const float* phi   = (const float*)d_in[2];
    const float* pmask = (const float*)d_in[3];
    const float* Wq    = (const float*)d_in[4];
    const float* Wk    = (const float*)d_in[5];
    const float* Wv    = (const float*)d_in[6];
    const void*  idx_i = d_in[7];
    const void*  idx_j = d_in[8];
    float* out = (float*)d_out;

    detect_kernel<<<1, 1>>>((const int*)idx_j);
    convert_kernel<<<(N_PAIRS + 255) / 256, 256>>>(idx_j, phi, pmask);
    project_kernel<<<(N_NODES + NODES_PER_BLOCK - 1) / NODES_PER_BLOCK, 256>>>(x, Wq, Wk, Wv);
    build_rowptr_kernel<<<(N_PAIRS + 255) / 256, 256>>>(idx_i);
    attn_kernel<<<(N_NODES + 7) / 8, 256>>>(w_ij, out);
}

// round 6
// speedup vs baseline: 1.0958x; 1.0190x over previous
#include <cuda_runtime.h>
#include <stdint.h>

#define N_NODES 100000
#define N_PAIRS 1600000
#define F 64
#define H 4
#define D 16

// Scratch (static __device__ — no runtime allocation allowed)
__device__ float g_q [(size_t)N_NODES * F];
__device__ float g_kv[(size_t)N_NODES * 2 * F];   // k row (64) | v row (64) per node
__device__ int   g_rowstart[N_NODES + 1];
__device__ int   g_idx_j[N_PAIRS];
__device__ float g_scale[N_PAIRS];

// ---------------------------------------------------------------------------
// Kernel 1 (prep): pair-parallel. Detects int64 vs int32 indices per block
// (cheap redundant check), converts idx_j to int, fuses phi*mask*rsqrt(D)
// into one scale, and builds CSR row offsets from the SORTED idx_i.
// ---------------------------------------------------------------------------
__global__ void prep_kernel(const void* __restrict__ idx_i,
                            const void* __restrict__ idx_j,
                            const float* __restrict__ phi,
                            const float* __restrict__ pmask)
{
    __shared__ int s_is64;
    if (threadIdx.x == 0) {
        // int64 values < 100000 -> all high words zero; int32 data -> random
        const int* v = (const int*)idx_j;
        int nz = 0;
        #pragma unroll
        for (int s = 0; s < 64; ++s) nz |= v[2 * s + 1];
        s_is64 = (nz == 0);
    }
    __syncthreads();

    const int p = blockIdx.x * 256 + threadIdx.x;
    if (p >= N_PAIRS) return;
    const int is64 = s_is64;

    g_idx_j[p] = is64 ? (int)((const long long*)idx_j)[p]
                      : ((const int*)idx_j)[p];
    g_scale[p] = phi[p] * pmask[p] * 0.25f;   // 1/sqrt(16)

    int i, prev;
    if (is64) {
        const long long* ii = (const long long*)idx_i;
        i    = (int)ii[p];
        prev = (p == 0) ? -1 : (int)ii[p - 1];
    } else {
        const int* ii = (const int*)idx_i;
        i    = ii[p];
        prev = (p == 0) ? -1 : ii[p - 1];
    }
    for (int node = prev + 1; node <= i; ++node)
        g_rowstart[node] = p;
    if (p == N_PAIRS - 1) {
        for (int node = i + 1; node <= N_NODES; ++node)
            g_rowstart[node] = N_PAIRS;
    }
}

// ---------------------------------------------------------------------------
// Kernel 2 (project): q -> g_q; k,v interleaved per node into g_kv.
// ---------------------------------------------------------------------------
#define NODES_PER_BLOCK 16

__global__ void project_kernel(const float* __restrict__ x,
                               const float* __restrict__ Wq,
                               const float* __restrict__ Wk,
                               const float* __restrict__ Wv)
{
    __shared__ float sW[3][H * D * D];
    __shared__ float sx[NODES_PER_BLOCK][F];

    const int tid = threadIdx.x;

    for (int idx = tid; idx < H * D * D; idx += 256) {
        sW[0][idx] = Wq[idx];
        sW[1][idx] = Wk[idx];
        sW[2][idx] = Wv[idx];
    }
    const int node0 = blockIdx.x * NODES_PER_BLOCK;
    for (int idx = tid; idx < NODES_PER_BLOCK * F; idx += 256) {
        int node = node0 + (idx >> 6);
        ((float*)sx)[idx] = (node < N_NODES) ? x[(size_t)node * F + (idx & 63)] : 0.f;
    }
    __syncthreads();

    const int nl = tid >> 4;
    const int e4 = tid & 15;
    const int h  = e4 >> 2;
    const int c4 = (e4 & 3) * 4;

    const int node = node0 + nl;
    if (node >= N_NODES) return;

    const float* xr = &sx[nl][h * D];

    float4 aq = make_float4(0.f, 0.f, 0.f, 0.f);
    float4 ak = aq, av = aq;

    #pragma unroll
    for (int d = 0; d < D; ++d) {
        float xd = xr[d];
        float4 wq = *(const float4*)&sW[0][h * 256 + d * 16 + c4];
        float4 wk = *(const float4*)&sW[1][h * 256 + d * 16 + c4];
        float4 wv = *(const float4*)&sW[2][h * 256 + d * 16 + c4];
        aq.x = fmaf(xd, wq.x, aq.x); aq.y = fmaf(xd, wq.y, aq.y);
        aq.z = fmaf(xd, wq.z, aq.z); aq.w = fmaf(xd, wq.w, aq.w);
        ak.x = fmaf(xd, wk.x, ak.x); ak.y = fmaf(xd, wk.y, ak.y);
        ak.z = fmaf(xd, wk.z, ak.z); ak.w = fmaf(xd, wk.w, ak.w);
        av.x = fmaf(xd, wv.x, av.x); av.y = fmaf(xd, wv.y, av.y);
        av.z = fmaf(xd, wv.z, av.z); av.w = fmaf(xd, wv.w, av.w);
    }

    *(float4*)&g_q [(size_t)node * F + e4 * 4]           = aq;
    *(float4*)&g_kv[(size_t)node * 2 * F + e4 * 4]       = ak;
    *(float4*)&g_kv[(size_t)node * 2 * F + F + e4 * 4]   = av;
}

// ---------------------------------------------------------------------------
// Kernel 3 (attn): warp-per-node fused attention + segment sum. Half-warp per
// pair slot, 4 pairs per warp iteration (unroll 2). Uniform trip count ->
// no shuffle divergence. w_ij read with streaming hint (__ldcs) to protect
// k/v residency in L2; output written with __stcs. No atomics.
// ---------------------------------------------------------------------------
__global__ void __launch_bounds__(256) attn_kernel(
    const float* __restrict__ w_ij,
    float* __restrict__ out)
{
    const int warp = (blockIdx.x * 256 + threadIdx.x) >> 5;
    const int lane = threadIdx.x & 31;
    if (warp >= N_NODES) return;
    const int half = lane >> 4;                 // pair slot within iteration
    const int sl   = lane & 15;                 // float4 slot within row
    const unsigned gmask = 0xFu << (lane & 28); // 4-lane head group

    const int p0 = g_rowstart[warp];
    const int p1 = g_rowstart[warp + 1];
    const int iters = (p1 - p0 + 3) >> 2;       // 4 pairs per iteration, warp-uniform

    const float4 q4 = *(const float4*)&g_q[(size_t)warp * F + sl * 4];

    float4 acc = make_float4(0.f, 0.f, 0.f, 0.f);

    for (int it = 0; it < iters; ++it) {
        const int pA  = p0 + 4 * it + half;
        const int pB  = pA + 2;
        const int pcA = min(pA, N_PAIRS - 1);   // clamp: in-bounds, zeroed via sA/sB
        const int pcB = min(pB, N_PAIRS - 1);

        const int   jA = g_idx_j[pcA];
        const int   jB = g_idx_j[pcB];
        const float sA = (pA < p1) ? g_scale[pcA] : 0.f;
        const float sB = (pB < p1) ? g_scale[pcB] : 0.f;

        const float4 wA = __ldcs((const float4*)(w_ij + (size_t)pcA * F) + sl);
        const float4 wB = __ldcs((const float4*)(w_ij + (size_t)pcB * F) + sl);

        const float* kvA = g_kv + (size_t)jA * 2 * F;
        const float* kvB = g_kv + (size_t)jB * 2 * F;
        const float4 kA = *((const float4*)kvA + sl);
        const float4 vA = *((const float4*)(kvA + F) + sl);
        const float4 kB = *((const float4*)kvB + sl);
        const float4 vB = *((const float4*)(kvB + F) + sl);

        float tA = q4.x * wA.x * kA.x;
        tA = fmaf(q4.y * wA.y, kA.y, tA);
        tA = fmaf(q4.z * wA.z, kA.z, tA);
        tA = fmaf(q4.w * wA.w, kA.w, tA);

        float tB = q4.x * wB.x * kB.x;
        tB = fmaf(q4.y * wB.y, kB.y, tB);
        tB = fmaf(q4.z * wB.z, kB.z, tB);
        tB = fmaf(q4.w * wB.w, kB.w, tB);

        tA += __shfl_xor_sync(gmask, tA, 1, 4);
        tA += __shfl_xor_sync(gmask, tA, 2, 4);
        tB += __shfl_xor_sync(gmask, tB, 1, 4);
        tB += __shfl_xor_sync(gmask, tB, 2, 4);

        const float aA = tA * sA;
        const float aB = tB * sB;
        acc.x = fmaf(aA, vA.x, acc.x); acc.x = fmaf(aB, vB.x, acc.x);
        acc.y = fmaf(aA, vA.y, acc.y); acc.y = fmaf(aB, vB.y, acc.y);
        acc.z = fmaf(aA, vA.z, acc.z); acc.z = fmaf(aB, vB.z, acc.z);
        acc.w = fmaf(aA, vA.w, acc.w); acc.w = fmaf(aB, vB.w, acc.w);
    }

    // merge the two half-warp accumulators (warp fully converged here)
    acc.x += __shfl_xor_sync(0xffffffffu, acc.x, 16);
    acc.y += __shfl_xor_sync(0xffffffffu, acc.y, 16);
    acc.z += __shfl_xor_sync(0xffffffffu, acc.z, 16);
    acc.w += __shfl_xor_sync(0xffffffffu, acc.w, 16);

    if (half == 0)
        __stcs((float4*)&out[(size_t)warp * F + sl * 4], acc);
}

// ---------------------------------------------------------------------------
extern "C" void kernel_launch(void* const* d_in, const int* in_sizes, int n_in,
                              void* d_out, int out_size)
{
    const float* x     = (const float*)d_in[0];
    const float* w_ij  = (const float*)d_in[1];
    const float* phi   = (const float*)d_in[2];
    const float* pmask = (const float*)d_in[3];
    const float* Wq    = (const float*)d_in[4];
    const float* Wk    = (const float*)d_in[5];
    const float* Wv    = (const float*)d_in[6];
    const void*  idx_i = d_in[7];
    const void*  idx_j = d_in[8];
    float* out = (float*)d_out;

    prep_kernel<<<(N_PAIRS + 255) / 256, 256>>>(idx_i, idx_j, phi, pmask);
    project_kernel<<<(N_NODES + NODES_PER_BLOCK - 1) / NODES_PER_BLOCK, 256>>>(x, Wq, Wk, Wv);
    attn_kernel<<<(N_NODES + 7) / 8, 256>>>(w_ij, out);
}